// round 7
// baseline (speedup 1.0000x reference)
#include <cuda_runtime.h>

// DeepFilterNet DF coef op, GB300 — R7: role split + fast-path ILP=4.
// spec  : [B=32, 1, T=1000, F=481, 2] f32
// coefs : [B, T, 5, 96, 2] f32
// alpha : [B, T, 1] f32
// out   : same as spec; first 96 bins = 5-tap complex FIR blended with alpha.
//
// Fast copy path is latency*concurrency bound; ILP=2 (R6) raised DRAM to 75%.
// ILP=4 doubles outstanding read bytes/warp again. Slow DF path unchanged.

#define B_DIM 32
#define T_DIM 1000
#define F_DIM 481
#define F_DF 96
#define ORDER 5

#define NROWPAIR 16000                 // 32000 rows / 2
#define NSLOW    (NROWPAIR * 97)       // 1,552,000 pairs
#define NFAST    (NROWPAIR * 384)      // 6,144,000 pairs
#define TPB      256
#define FAST_ILP 4
#define SLOW_BLOCKS ((NSLOW + TPB - 1) / TPB)          // 6063
#define FAST_BLOCKS (NFAST / (FAST_ILP * TPB))          // 6000 (exact)

__device__ __forceinline__ float2 df_elem(
    const float2* __restrict__ spec,
    const float2* __restrict__ coefs,
    const float*  __restrict__ alpha,
    int bt, int f, float2 s)
{
    int t = bt % T_DIM;
    const float2* cptr = coefs + (size_t)bt * (ORDER * F_DF) + f;

    float re = 0.0f, im = 0.0f;
    #pragma unroll
    for (int i = 0; i < ORDER; i++) {
        int tt = t + i - 2;                       // ORDER - LOOKAHEAD - 1 = 2
        float2 w = make_float2(0.0f, 0.0f);
        if (tt >= 0 && tt < T_DIM)
            w = spec[(size_t)(bt + i - 2) * F_DIM + f];
        float2 c = cptr[(size_t)i * F_DF];
        re = fmaf(w.x, c.x, re);
        re = fmaf(-w.y, c.y, re);
        im = fmaf(w.y, c.x, im);
        im = fmaf(w.x, c.y, im);
    }

    float a  = alpha[bt];
    float na = 1.0f - a;
    return make_float2(fmaf(re, a, s.x * na), fmaf(im, a, s.y * na));
}

// map fast-path linear index g -> pair index p
__device__ __forceinline__ int fast_map(int g)
{
    int rp = g / 384;
    int k  = g - rp * 384;
    // k <  192: even row, p = 481*rp + 48 + k
    // k >= 192: odd  row, p = 481*rp + 97 + k
    return 481 * rp + k + ((k < 192) ? 48 : 97);
}

__global__ void __launch_bounds__(TPB) df_coef_kernel(
    const float4* __restrict__ spec4,
    const float2* __restrict__ spec2,
    const float2* __restrict__ coefs,
    const float*  __restrict__ alpha,
    float4* __restrict__ out4)
{
    if (blockIdx.x >= SLOW_BLOCKS) {
        // ---- FAST: passthrough copy, 4 pairs/thread, loads front-batched ----
        int fb = blockIdx.x - SLOW_BLOCKS;
        int gb = fb * (FAST_ILP * TPB) + threadIdx.x;   // all in range (exact)

        int p[FAST_ILP];
        float4 v[FAST_ILP];
        #pragma unroll
        for (int j = 0; j < FAST_ILP; j++)
            p[j] = fast_map(gb + j * TPB);
        #pragma unroll
        for (int j = 0; j < FAST_ILP; j++)
            v[j] = __ldcs(&spec4[p[j]]);
        #pragma unroll
        for (int j = 0; j < FAST_ILP; j++)
            __stcs(&out4[p[j]], v[j]);
        return;
    }

    // ---- SLOW: pairs containing at least one DF bin ----
    int s = blockIdx.x * TPB + threadIdx.x;
    if (s >= NSLOW) return;
    int rp = s / 97;
    int k  = s - rp * 97;
    int r0 = 2 * rp;

    int p, bt0, f0, bt1, f1;
    if (k < 48) {                 // even row, both elements DF
        p = 481 * rp + k;
        bt0 = r0;     f0 = 2 * k;
        bt1 = r0;     f1 = f0 + 1;
    } else if (k < 96) {          // odd row
        p = 481 * rp + k + 193;
        bt0 = r0 + 1; f0 = 2 * (k - 48) + 1;
        bt1 = r0 + 1; f1 = f0 + 1;          // f1 == 96 when k == 95 (pass)
    } else {                      // boundary pair: (r0, 480) | (r0+1, 0)
        p = 481 * rp + 240;
        bt0 = r0;     f0 = 480;             // passthrough
        bt1 = r0 + 1; f1 = 0;               // DF
    }

    float4 s4 = spec4[p];
    float2 e0 = make_float2(s4.x, s4.y);
    float2 e1 = make_float2(s4.z, s4.w);

    float2 r0v = (f0 < F_DF) ? df_elem(spec2, coefs, alpha, bt0, f0, e0) : e0;
    float2 r1v = (f1 < F_DF) ? df_elem(spec2, coefs, alpha, bt1, f1, e1) : e1;

    __stcs(&out4[p], make_float4(r0v.x, r0v.y, r1v.x, r1v.y));
}

extern "C" void kernel_launch(void* const* d_in, const int* in_sizes, int n_in,
                              void* d_out, int out_size)
{
    const float4* spec4 = (const float4*)d_in[0];
    const float2* spec2 = (const float2*)d_in[0];
    const float2* coefs = (const float2*)d_in[1];
    const float*  alpha = (const float*)d_in[2];

    df_coef_kernel<<<SLOW_BLOCKS + FAST_BLOCKS, TPB>>>(
        spec4, spec2, coefs, alpha, (float4*)d_out);
}

// round 8
// speedup vs baseline: 1.0344x; 1.0344x over previous
#include <cuda_runtime.h>

// DeepFilterNet DF coef op, GB300 — R8: R6 (role split, fast ILP=2) with
// fast-path loads DEFAULT-cached (A/B vs __ldcs; R4 showed ldcs hurt
// stream-once coef reads). Stores stay __stcs so 123MB of write traffic
// doesn't evict the DF tap lines from L2.
//
// spec  : [B=32, 1, T=1000, F=481, 2] f32
// coefs : [B, T, 5, 96, 2] f32
// alpha : [B, T, 1] f32
// out   : same as spec; first 96 bins = 5-tap complex FIR blended with alpha.

#define B_DIM 32
#define T_DIM 1000
#define F_DIM 481
#define F_DF 96
#define ORDER 5

#define NROWPAIR 16000                 // 32000 rows / 2
#define NSLOW    (NROWPAIR * 97)       // 1,552,000 pairs
#define NFAST    (NROWPAIR * 384)      // 6,144,000 pairs
#define TPB      256
#define SLOW_BLOCKS ((NSLOW + TPB - 1) / TPB)     // 6063
#define FAST_BLOCKS (NFAST / (2 * TPB))           // 12000 (exact)

__device__ __forceinline__ float2 df_elem(
    const float2* __restrict__ spec,
    const float2* __restrict__ coefs,
    const float*  __restrict__ alpha,
    int bt, int f, float2 s)
{
    int t = bt % T_DIM;
    const float2* cptr = coefs + (size_t)bt * (ORDER * F_DF) + f;

    float re = 0.0f, im = 0.0f;
    #pragma unroll
    for (int i = 0; i < ORDER; i++) {
        int tt = t + i - 2;                       // ORDER - LOOKAHEAD - 1 = 2
        float2 w = make_float2(0.0f, 0.0f);
        if (tt >= 0 && tt < T_DIM)
            w = spec[(size_t)(bt + i - 2) * F_DIM + f];
        float2 c = cptr[(size_t)i * F_DF];
        re = fmaf(w.x, c.x, re);
        re = fmaf(-w.y, c.y, re);
        im = fmaf(w.y, c.x, im);
        im = fmaf(w.x, c.y, im);
    }

    float a  = alpha[bt];
    float na = 1.0f - a;
    return make_float2(fmaf(re, a, s.x * na), fmaf(im, a, s.y * na));
}

// map fast-path linear index g -> pair index p
__device__ __forceinline__ int fast_map(int g)
{
    int rp = g / 384;
    int k  = g - rp * 384;
    // k <  192: even row, p = 481*rp + 48 + k
    // k >= 192: odd  row, p = 481*rp + 97 + k
    return 481 * rp + k + ((k < 192) ? 48 : 97);
}

__global__ void __launch_bounds__(TPB) df_coef_kernel(
    const float4* __restrict__ spec4,
    const float2* __restrict__ spec2,
    const float2* __restrict__ coefs,
    const float*  __restrict__ alpha,
    float4* __restrict__ out4)
{
    if (blockIdx.x >= SLOW_BLOCKS) {
        // ---- FAST: passthrough copy, 2 pairs/thread, loads front-batched ----
        int fb = blockIdx.x - SLOW_BLOCKS;
        int g0 = fb * (2 * TPB) + threadIdx.x;     // < NFAST guaranteed
        int g1 = g0 + TPB;
        int p0 = fast_map(g0);
        int p1 = fast_map(g1);
        float4 v0 = spec4[p0];                     // default cache (A/B vs ldcs)
        float4 v1 = spec4[p1];
        __stcs(&out4[p0], v0);
        __stcs(&out4[p1], v1);
        return;
    }

    // ---- SLOW: pairs containing at least one DF bin ----
    int s = blockIdx.x * TPB + threadIdx.x;
    if (s >= NSLOW) return;
    int rp = s / 97;
    int k  = s - rp * 97;
    int r0 = 2 * rp;

    int p, bt0, f0, bt1, f1;
    if (k < 48) {                 // even row, both elements DF
        p = 481 * rp + k;
        bt0 = r0;     f0 = 2 * k;
        bt1 = r0;     f1 = f0 + 1;
    } else if (k < 96) {          // odd row
        p = 481 * rp + k + 193;
        bt0 = r0 + 1; f0 = 2 * (k - 48) + 1;
        bt1 = r0 + 1; f1 = f0 + 1;          // f1 == 96 when k == 95 (pass)
    } else {                      // boundary pair: (r0, 480) | (r0+1, 0)
        p = 481 * rp + 240;
        bt0 = r0;     f0 = 480;             // passthrough
        bt1 = r0 + 1; f1 = 0;               // DF
    }

    float4 s4 = spec4[p];
    float2 e0 = make_float2(s4.x, s4.y);
    float2 e1 = make_float2(s4.z, s4.w);

    float2 r0v = (f0 < F_DF) ? df_elem(spec2, coefs, alpha, bt0, f0, e0) : e0;
    float2 r1v = (f1 < F_DF) ? df_elem(spec2, coefs, alpha, bt1, f1, e1) : e1;

    __stcs(&out4[p], make_float4(r0v.x, r0v.y, r1v.x, r1v.y));
}

extern "C" void kernel_launch(void* const* d_in, const int* in_sizes, int n_in,
                              void* d_out, int out_size)
{
    const float4* spec4 = (const float4*)d_in[0];
    const float2* spec2 = (const float2*)d_in[0];
    const float2* coefs = (const float2*)d_in[1];
    const float*  alpha = (const float*)d_in[2];

    df_coef_kernel<<<SLOW_BLOCKS + FAST_BLOCKS, TPB>>>(
        spec4, spec2, coefs, alpha, (float4*)d_out);
}